// round 1
// baseline (speedup 1.0000x reference)
#include <cuda_runtime.h>

// ---------------------------------------------------------------------------
// AxisAttention baseline: fp32 register-blocked SGEMM chain + row softmax.
// B=4, N=2048, DQ=DKV=DA=512. All dims multiples of 128 -> no bounds checks.
// ---------------------------------------------------------------------------

constexpr int BB  = 4;
constexpr int SEQ = 2048;
constexpr int DIM = 512;
constexpr float SCALE_F = 22.62741699796952f;  // sqrt(512), MULTIPLIED per reference

// Scratch (device globals; no runtime allocation allowed)
__device__ float g_q[(size_t)BB * SEQ * DIM];           // 16 MB
__device__ float g_k[(size_t)BB * SEQ * DIM];           // 16 MB
__device__ float g_v[(size_t)BB * SEQ * DIM];           // 16 MB
__device__ float g_s[(size_t)BB * SEQ * SEQ];           // 64 MB (scores / probs)
__device__ float g_o[(size_t)BB * SEQ * DIM];           // 16 MB

// Load a 128(rows) x 16(cols) tile from row-major src (leading dim = ld),
// transposed into dst[k][m]. Used for A tiles and for B tiles when B is [N,K].
__device__ __forceinline__ void load_tile_trans(
    const float* __restrict__ src, int row0, int k0, int ld,
    float dst[16][128], int t)
{
    const int r = t >> 2;          // 0..63
    const int c = (t & 3) << 2;    // 0,4,8,12
#pragma unroll
    for (int i = 0; i < 2; i++) {
        const float4 v = *reinterpret_cast<const float4*>(
            src + (size_t)(row0 + r + i * 64) * ld + k0 + c);
        dst[c + 0][r + i * 64] = v.x;
        dst[c + 1][r + i * 64] = v.y;
        dst[c + 2][r + i * 64] = v.z;
        dst[c + 3][r + i * 64] = v.w;
    }
}

// Load a 16(k) x 128(n) tile from row-major src [K, N] (leading dim = ld)
// directly into dst[k][n].
__device__ __forceinline__ void load_tile_direct(
    const float* __restrict__ src, int k0, int n0, int ld,
    float dst[16][128], int t)
{
    const int kr = t >> 5;         // 0..7
    const int c  = (t & 31) << 2;  // 0..124
#pragma unroll
    for (int i = 0; i < 2; i++) {
        *reinterpret_cast<float4*>(&dst[kr + i * 8][c]) =
            *reinterpret_cast<const float4*>(
                src + (size_t)(k0 + kr + i * 8) * ld + n0 + c);
    }
}

// C[z] = alpha * A[z] @ op(B[z]) (+ bias) (+ resid), 128x128x16 tiles,
// 256 threads, 8x8 per-thread microtile.
// TB=false: B is [K, Nc] row-major.  TB=true: B is [Nc, K] row-major (B^T).
template <bool TB>
__global__ void __launch_bounds__(256, 2) gemm128(
    const float* __restrict__ A, const float* __restrict__ Bm,
    float* __restrict__ C,
    int Nc, int K,
    size_t sA, size_t sB, size_t sC,
    float alpha,
    const float* __restrict__ bias,
    const float* __restrict__ resid)
{
    __shared__ float As[16][128];
    __shared__ float Bs[16][128];

    const int t  = threadIdx.x;
    const int tx = t & 15;
    const int ty = t >> 4;
    const int n0 = blockIdx.x * 128;
    const int m0 = blockIdx.y * 128;
    const int z  = blockIdx.z;

    A  += (size_t)z * sA;
    Bm += (size_t)z * sB;
    C  += (size_t)z * sC;

    float acc[8][8];
#pragma unroll
    for (int i = 0; i < 8; i++)
#pragma unroll
        for (int j = 0; j < 8; j++) acc[i][j] = 0.0f;

    for (int k0 = 0; k0 < K; k0 += 16) {
        load_tile_trans(A, m0, k0, K, As, t);
        if (TB) load_tile_trans(Bm, n0, k0, K, Bs, t);
        else    load_tile_direct(Bm, k0, n0, Nc, Bs, t);
        __syncthreads();

#pragma unroll
        for (int kk = 0; kk < 16; kk++) {
            float a[8], b[8];
#pragma unroll
            for (int i = 0; i < 8; i++) a[i] = As[kk][ty * 8 + i];
#pragma unroll
            for (int j = 0; j < 8; j++) b[j] = Bs[kk][tx * 8 + j];
#pragma unroll
            for (int i = 0; i < 8; i++)
#pragma unroll
                for (int j = 0; j < 8; j++) acc[i][j] += a[i] * b[j];
        }
        __syncthreads();
    }

    // Epilogue: alpha scale, optional bias[n], optional resid[m,n], float4 stores
#pragma unroll
    for (int i = 0; i < 8; i++) {
        const int row = m0 + ty * 8 + i;
#pragma unroll
        for (int j = 0; j < 8; j += 4) {
            const int col = n0 + tx * 8 + j;
            float4 v;
            v.x = alpha * acc[i][j + 0];
            v.y = alpha * acc[i][j + 1];
            v.z = alpha * acc[i][j + 2];
            v.w = alpha * acc[i][j + 3];
            if (bias) {
                v.x += bias[col + 0];
                v.y += bias[col + 1];
                v.z += bias[col + 2];
                v.w += bias[col + 3];
            }
            if (resid) {
                const float4 r = *reinterpret_cast<const float4*>(
                    resid + (size_t)row * Nc + col);
                v.x += r.x; v.y += r.y; v.z += r.z; v.w += r.w;
            }
            *reinterpret_cast<float4*>(&C[(size_t)row * Nc + col]) = v;
        }
    }
}

// Row softmax over rows of length SEQ (2048). One block (256 thr) per row.
__global__ void __launch_bounds__(256) softmax_rows(float* __restrict__ S)
{
    const size_t row = blockIdx.x;
    float* p = S + row * (size_t)SEQ;
    const int t = threadIdx.x;

    float vals[8];
    float m = -3.402823466e38f;
#pragma unroll
    for (int i = 0; i < 8; i++) {
        vals[i] = p[t + i * 256];
        m = fmaxf(m, vals[i]);
    }

    __shared__ float red[256];
    red[t] = m;
    __syncthreads();
#pragma unroll
    for (int s = 128; s > 0; s >>= 1) {
        if (t < s) red[t] = fmaxf(red[t], red[t + s]);
        __syncthreads();
    }
    m = red[0];
    __syncthreads();

    float sum = 0.0f;
#pragma unroll
    for (int i = 0; i < 8; i++) {
        vals[i] = __expf(vals[i] - m);
        sum += vals[i];
    }
    red[t] = sum;
    __syncthreads();
#pragma unroll
    for (int s = 128; s > 0; s >>= 1) {
        if (t < s) red[t] += red[t + s];
        __syncthreads();
    }
    const float inv = 1.0f / red[0];
#pragma unroll
    for (int i = 0; i < 8; i++)
        p[t + i * 256] = vals[i] * inv;
}

extern "C" void kernel_launch(void* const* d_in, const int* in_sizes, int n_in,
                              void* d_out, int out_size)
{
    (void)in_sizes; (void)n_in; (void)out_size;

    const float* query     = (const float*)d_in[0];
    const float* key_value = (const float*)d_in[1];
    const float* Wq = (const float*)d_in[2];
    const float* bq = (const float*)d_in[3];
    const float* Wk = (const float*)d_in[4];
    const float* bk = (const float*)d_in[5];
    const float* Wv = (const float*)d_in[6];
    const float* bv = (const float*)d_in[7];
    const float* Wo = (const float*)d_in[8];
    const float* bo = (const float*)d_in[9];
    float* out = (float*)d_out;

    float *q, *k, *v, *s, *o;
    cudaGetSymbolAddress((void**)&q, g_q);
    cudaGetSymbolAddress((void**)&k, g_k);
    cudaGetSymbolAddress((void**)&v, g_v);
    cudaGetSymbolAddress((void**)&s, g_s);
    cudaGetSymbolAddress((void**)&o, g_o);

    const dim3 blk(256);
    const size_t sQKV = (size_t)SEQ * DIM;   // per-batch stride for q/k/v/o
    const size_t sS   = (size_t)SEQ * SEQ;   // per-batch stride for scores

    // 1) q/k/v projections: [8192,512] @ [512,512] + bias
    {
        dim3 grid(DIM / 128, (BB * SEQ) / 128, 1);
        gemm128<false><<<grid, blk>>>(query,     Wq, q, DIM, DIM, 0, 0, 0, 1.0f, bq, nullptr);
        gemm128<false><<<grid, blk>>>(key_value, Wk, k, DIM, DIM, 0, 0, 0, 1.0f, bk, nullptr);
        gemm128<false><<<grid, blk>>>(key_value, Wv, v, DIM, DIM, 0, 0, 0, 1.0f, bv, nullptr);
    }

    // 2) scores: S[b] = sqrt(512) * q[b] @ k[b]^T   (NT, batched over z)
    {
        dim3 grid(SEQ / 128, SEQ / 128, BB);
        gemm128<true><<<grid, blk>>>(q, k, s, SEQ, DIM, sQKV, sQKV, sS,
                                     SCALE_F, nullptr, nullptr);
    }

    // 3) softmax over last dim (rows of length 2048)
    softmax_rows<<<BB * SEQ, blk>>>(s);

    // 4) O[b] = P[b] @ v[b]   (NN, K=2048, batched)
    {
        dim3 grid(DIM / 128, SEQ / 128, BB);
        gemm128<false><<<grid, blk>>>(s, v, o, DIM, SEQ, sS, sQKV, sQKV,
                                      1.0f, nullptr, nullptr);
    }

    // 5) out = query + O @ Wo + bo
    {
        dim3 grid(DIM / 128, (BB * SEQ) / 128, 1);
        gemm128<false><<<grid, blk>>>(o, Wo, out, DIM, DIM, 0, 0, 0,
                                      1.0f, bo, query);
    }
}

// round 3
// speedup vs baseline: 1.7429x; 1.7429x over previous
#include <cuda_runtime.h>
#include <cstdint>

// ===========================================================================
// AxisAttention via mma.sync tf32 (HMMA fallback path on sm_103):
// 3xTF32 split precision for q/k projections and QK^T; single-pass tf32 for
// v-proj, PV, out-proj. B=4, N=2048, D=DA=512.
// ===========================================================================

constexpr int BB  = 4;
constexpr int SEQ = 2048;
constexpr int DIM = 512;
constexpr float SCALE_F = 22.62741699796952f;  // sqrt(512), multiplied

// ---------------- device global scratch (no runtime allocation) -----------
__device__ float g_query_hi[(size_t)BB * SEQ * DIM];
__device__ float g_query_lo[(size_t)BB * SEQ * DIM];
__device__ float g_kv_hi[(size_t)BB * SEQ * DIM];
__device__ float g_kv_lo[(size_t)BB * SEQ * DIM];
__device__ float g_q_hi[(size_t)BB * SEQ * DIM];
__device__ float g_q_lo[(size_t)BB * SEQ * DIM];
__device__ float g_k_hi[(size_t)BB * SEQ * DIM];
__device__ float g_k_lo[(size_t)BB * SEQ * DIM];
__device__ float g_vt[(size_t)BB * DIM * SEQ];        // V^T per batch [DIM, SEQ]
__device__ float g_s[(size_t)BB * SEQ * SEQ];         // scores / probs
__device__ float g_o[(size_t)BB * SEQ * DIM];
__device__ float g_wqt_hi[DIM * DIM];
__device__ float g_wqt_lo[DIM * DIM];
__device__ float g_wkt_hi[DIM * DIM];
__device__ float g_wkt_lo[DIM * DIM];
__device__ float g_wvt[DIM * DIM];
__device__ float g_wot[DIM * DIM];

// ---------------- helpers ---------------------------------------------------
__device__ __forceinline__ uint32_t smem_u32(const void* p) {
    uint32_t a;
    asm("{ .reg .u64 t; cvta.to.shared.u64 t, %1; cvt.u32.u64 %0, t; }"
        : "=r"(a) : "l"(p));
    return a;
}
__device__ __forceinline__ float tf32_rna(float x) {
    uint32_t u;
    asm("cvt.rna.tf32.f32 %0, %1;" : "=r"(u) : "f"(x));
    return __uint_as_float(u);
}
__device__ __forceinline__ void cp16(uint32_t saddr, const void* g) {
    asm volatile("cp.async.cg.shared.global [%0], [%1], 16;"
                 :: "r"(saddr), "l"(g) : "memory");
}
__device__ __forceinline__ void cp_commit() {
    asm volatile("cp.async.commit_group;" ::: "memory");
}
template <int N>
__device__ __forceinline__ void cp_wait() {
    asm volatile("cp.async.wait_group %0;" :: "n"(N) : "memory");
}

// mma.sync m16n8k8 tf32: c += a(16x8) * b(8x8)
__device__ __forceinline__ void mma8(float* c, const float* a, const float* b) {
    asm volatile(
        "mma.sync.aligned.m16n8k8.row.col.f32.tf32.tf32.f32 "
        "{%0,%1,%2,%3}, {%4,%5,%6,%7}, {%8,%9}, {%0,%1,%2,%3};"
        : "+f"(c[0]), "+f"(c[1]), "+f"(c[2]), "+f"(c[3])
        : "r"(__float_as_uint(a[0])), "r"(__float_as_uint(a[1])),
          "r"(__float_as_uint(a[2])), "r"(__float_as_uint(a[3])),
          "r"(__float_as_uint(b[0])), "r"(__float_as_uint(b[1])));
}

// ---------------- tiles: 128 rows x 16 k-floats, row stride 20 floats ------
constexpr int LDW    = 20;            // padded row stride (floats)
constexpr int TILE_F = 128 * LDW;     // floats per tile
constexpr int TILE_B = TILE_F * 4;    // bytes per tile (10240)

__device__ __forceinline__ void load_tile_async(
    uint32_t sbase, const float* __restrict__ g, int ld, int tid)
{
#pragma unroll
    for (int i = 0; i < 2; i++) {
        const int id = tid + i * 256;     // 0..511 float4s
        const int r  = id >> 2;
        const int c4 = (id & 3) << 2;
        cp16(sbase + (uint32_t)(r * LDW + c4) * 4,
             g + (size_t)r * ld + c4);
    }
}

// ---------------- main GEMM -------------------------------------------------
// D[m,n] = alpha * sum_k A[m,k]*B[n,k] (+bias[n]) (+resid), 128x128 CTA tile.
// 256 threads, 8 warps, warp tile 64x32 (4x4 m16n8 subtiles).
// PASSES: 1 or 3 (3xTF32). EPI: 0=split hi/lo+bias, 1=transposed VT+bias,
// 2=alpha scale, 3=plain tf32-rounded, 4=bias+residual.
template <int PASSES, int EPI>
__global__ void __launch_bounds__(256, (PASSES == 3) ? 1 : 2) gemm_mma(
    const float* __restrict__ Ahi, const float* __restrict__ Alo,
    const float* __restrict__ Bhi, const float* __restrict__ Blo,
    float* __restrict__ C, float* __restrict__ C2,
    const float* __restrict__ bias, const float* __restrict__ resid,
    int K, int lda, int ldb, int ldc,
    size_t sA, size_t sB, size_t sC, float alpha)
{
    constexpr int NT = (PASSES == 3) ? 4 : 2;   // tiles per stage
    extern __shared__ float smf[];
    const uint32_t sb = smem_u32(smf);

    const int tid    = threadIdx.x;
    const int lane   = tid & 31;
    const int wid    = tid >> 5;
    const int warp_m = wid >> 2;      // 0..1
    const int warp_n = wid & 3;       // 0..3
    const int n0 = blockIdx.x * 128;
    const int m0 = blockIdx.y * 128;
    const int z  = blockIdx.z;

    const float* A0 = Ahi + (size_t)z * sA + (size_t)m0 * lda;
    const float* B0 = Bhi + (size_t)z * sB + (size_t)n0 * ldb;
    const float* A1 = (PASSES == 3) ? Alo + (size_t)z * sA + (size_t)m0 * lda : nullptr;
    const float* B1 = (PASSES == 3) ? Blo + (size_t)z * sB + (size_t)n0 * ldb : nullptr;

    float acc[4][4][4];
#pragma unroll
    for (int i = 0; i < 4; i++)
#pragma unroll
        for (int j = 0; j < 4; j++)
#pragma unroll
            for (int l = 0; l < 4; l++) acc[i][j][l] = 0.0f;

    const int nch = K / 16;

    auto load_stage = [&](int buf, int c) {
        const uint32_t st = sb + (uint32_t)buf * NT * TILE_B;
        load_tile_async(st,              A0 + c * 16, lda, tid);
        load_tile_async(st + TILE_B,     B0 + c * 16, ldb, tid);
        if (PASSES == 3) {
            load_tile_async(st + 2 * TILE_B, A1 + c * 16, lda, tid);
            load_tile_async(st + 3 * TILE_B, B1 + c * 16, ldb, tid);
        }
    };

    load_stage(0, 0);
    cp_commit();

    const int arow0 = warp_m * 64 + (lane >> 2);
    const int bcol0 = warp_n * 32 + (lane >> 2);
    const int kq    = lane & 3;

    for (int c = 0; c < nch; c++) {
        if (c + 1 < nch) {
            load_stage((c + 1) & 1, c + 1);
            cp_commit();
            cp_wait<1>();
        } else {
            cp_wait<0>();
        }
        __syncthreads();

        const float* st  = smf + (size_t)(c & 1) * NT * TILE_F;
        const float* Ath = st;
        const float* Bth = st + TILE_F;
        const float* Atl = st + 2 * TILE_F;
        const float* Btl = st + 3 * TILE_F;

#pragma unroll
        for (int kk = 0; kk < 16; kk += 8) {
            float a[4][4], b[4][2];
            // hi fragments
#pragma unroll
            for (int i = 0; i < 4; i++) {
                const float* r0 = Ath + (size_t)(arow0 + i * 16) * LDW + kk + kq;
                a[i][0] = r0[0];
                a[i][1] = r0[8 * LDW];
                a[i][2] = r0[4];
                a[i][3] = r0[8 * LDW + 4];
            }
#pragma unroll
            for (int j = 0; j < 4; j++) {
                const float* r0 = Bth + (size_t)(bcol0 + j * 8) * LDW + kk + kq;
                b[j][0] = r0[0];
                b[j][1] = r0[4];
            }
#pragma unroll
            for (int i = 0; i < 4; i++)
#pragma unroll
                for (int j = 0; j < 4; j++) mma8(acc[i][j], a[i], b[j]);

            if (PASSES == 3) {
                // A_hi * B_lo
                float bl[4][2];
#pragma unroll
                for (int j = 0; j < 4; j++) {
                    const float* r0 = Btl + (size_t)(bcol0 + j * 8) * LDW + kk + kq;
                    bl[j][0] = r0[0];
                    bl[j][1] = r0[4];
                }
#pragma unroll
                for (int i = 0; i < 4; i++)
#pragma unroll
                    for (int j = 0; j < 4; j++) mma8(acc[i][j], a[i], bl[j]);
                // A_lo * B_hi
                float al[4][4];
#pragma unroll
                for (int i = 0; i < 4; i++) {
                    const float* r0 = Atl + (size_t)(arow0 + i * 16) * LDW + kk + kq;
                    al[i][0] = r0[0];
                    al[i][1] = r0[8 * LDW];
                    al[i][2] = r0[4];
                    al[i][3] = r0[8 * LDW + 4];
                }
#pragma unroll
                for (int i = 0; i < 4; i++)
#pragma unroll
                    for (int j = 0; j < 4; j++) mma8(acc[i][j], al[i], b[j]);
            }
        }
        __syncthreads();
    }

    // ---------------- epilogue ----------------
    float* Cz = C + (size_t)z * sC;
#pragma unroll
    for (int i = 0; i < 4; i++) {
#pragma unroll
        for (int j = 0; j < 4; j++) {
            const float* a4 = acc[i][j];
            const int r0 = m0 + warp_m * 64 + i * 16 + (lane >> 2);
            const int c0 = n0 + warp_n * 32 + j * 8 + 2 * (lane & 3);
            if (EPI == 0) {            // split hi/lo with bias (q/k proj)
                float* C2z = C2 + (size_t)z * sC;
                const float bx = bias[c0], by = bias[c0 + 1];
                const float v0 = a4[0] + bx, v1 = a4[1] + by;
                const float v2 = a4[2] + bx, v3 = a4[3] + by;
                float2 h0, l0, h1, l1;
                h0.x = tf32_rna(v0); l0.x = tf32_rna(v0 - h0.x);
                h0.y = tf32_rna(v1); l0.y = tf32_rna(v1 - h0.y);
                h1.x = tf32_rna(v2); l1.x = tf32_rna(v2 - h1.x);
                h1.y = tf32_rna(v3); l1.y = tf32_rna(v3 - h1.y);
                *reinterpret_cast<float2*>(&Cz[(size_t)r0 * ldc + c0]) = h0;
                *reinterpret_cast<float2*>(&Cz[(size_t)(r0 + 8) * ldc + c0]) = h1;
                *reinterpret_cast<float2*>(&C2z[(size_t)r0 * ldc + c0]) = l0;
                *reinterpret_cast<float2*>(&C2z[(size_t)(r0 + 8) * ldc + c0]) = l1;
            } else if (EPI == 1) {     // transposed VT[b][dim][seq] + bias
                const float bx = bias[c0], by = bias[c0 + 1];
                const int b0i = r0 >> 11,      sx0 = r0 & (SEQ - 1);
                const int b1i = (r0 + 8) >> 11, sx1 = (r0 + 8) & (SEQ - 1);
                float* p0 = C + (size_t)b0i * DIM * SEQ;
                float* p1 = C + (size_t)b1i * DIM * SEQ;
                p0[(size_t)c0 * SEQ + sx0]       = tf32_rna(a4[0] + bx);
                p0[(size_t)(c0 + 1) * SEQ + sx0] = tf32_rna(a4[1] + by);
                p1[(size_t)c0 * SEQ + sx1]       = tf32_rna(a4[2] + bx);
                p1[(size_t)(c0 + 1) * SEQ + sx1] = tf32_rna(a4[3] + by);
            } else if (EPI == 2) {     // alpha scale (scores)
                float2 v0, v1;
                v0.x = alpha * a4[0]; v0.y = alpha * a4[1];
                v1.x = alpha * a4[2]; v1.y = alpha * a4[3];
                *reinterpret_cast<float2*>(&Cz[(size_t)r0 * ldc + c0]) = v0;
                *reinterpret_cast<float2*>(&Cz[(size_t)(r0 + 8) * ldc + c0]) = v1;
            } else if (EPI == 3) {     // plain tf32-rounded (O)
                float2 v0, v1;
                v0.x = tf32_rna(a4[0]); v0.y = tf32_rna(a4[1]);
                v1.x = tf32_rna(a4[2]); v1.y = tf32_rna(a4[3]);
                *reinterpret_cast<float2*>(&Cz[(size_t)r0 * ldc + c0]) = v0;
                *reinterpret_cast<float2*>(&Cz[(size_t)(r0 + 8) * ldc + c0]) = v1;
            } else {                   // bias + residual (final out)
                const float bx = bias[c0], by = bias[c0 + 1];
                const float2 rs0 = *reinterpret_cast<const float2*>(
                    &resid[(size_t)r0 * ldc + c0]);
                const float2 rs1 = *reinterpret_cast<const float2*>(
                    &resid[(size_t)(r0 + 8) * ldc + c0]);
                float2 v0, v1;
                v0.x = a4[0] + bx + rs0.x; v0.y = a4[1] + by + rs0.y;
                v1.x = a4[2] + bx + rs1.x; v1.y = a4[3] + by + rs1.y;
                *reinterpret_cast<float2*>(&Cz[(size_t)r0 * ldc + c0]) = v0;
                *reinterpret_cast<float2*>(&Cz[(size_t)(r0 + 8) * ldc + c0]) = v1;
            }
        }
    }
}

// ---------------- prep kernels ---------------------------------------------
__global__ void split_arr(const float4* __restrict__ in,
                          float4* __restrict__ hi, float4* __restrict__ lo, int n4)
{
    int i = blockIdx.x * 256 + threadIdx.x;
    if (i >= n4) return;
    float4 v = in[i];
    float4 h, l;
    h.x = tf32_rna(v.x); l.x = tf32_rna(v.x - h.x);
    h.y = tf32_rna(v.y); l.y = tf32_rna(v.y - h.y);
    h.z = tf32_rna(v.z); l.z = tf32_rna(v.z - h.z);
    h.w = tf32_rna(v.w); l.w = tf32_rna(v.w - h.w);
    hi[i] = h; lo[i] = l;
}

template <bool SPLIT>
__global__ void wprep(const float* __restrict__ W,
                      float* __restrict__ Thi, float* __restrict__ Tlo)
{
    int idx = blockIdx.x * 256 + threadIdx.x;   // idx = n*512 + k
    int n = idx >> 9, k = idx & 511;
    float w = W[k * DIM + n];
    float h = tf32_rna(w);
    Thi[idx] = h;
    if (SPLIT) Tlo[idx] = tf32_rna(w - h);
}

// ---------------- softmax (rows of 2048), output tf32-rounded --------------
__global__ void __launch_bounds__(256) softmax_rows(float* __restrict__ S)
{
    const size_t row = blockIdx.x;
    float* p = S + row * (size_t)SEQ;
    const int t = threadIdx.x;
    float vals[8];
    float m = -3.402823466e38f;
#pragma unroll
    for (int i = 0; i < 8; i++) { vals[i] = p[t + i * 256]; m = fmaxf(m, vals[i]); }
    __shared__ float red[256];
    red[t] = m; __syncthreads();
#pragma unroll
    for (int s = 128; s > 0; s >>= 1) { if (t < s) red[t] = fmaxf(red[t], red[t+s]); __syncthreads(); }
    m = red[0]; __syncthreads();
    float sum = 0.0f;
#pragma unroll
    for (int i = 0; i < 8; i++) { vals[i] = __expf(vals[i] - m); sum += vals[i]; }
    red[t] = sum; __syncthreads();
#pragma unroll
    for (int s = 128; s > 0; s >>= 1) { if (t < s) red[t] += red[t+s]; __syncthreads(); }
    const float inv = 1.0f / red[0];
#pragma unroll
    for (int i = 0; i < 8; i++) p[t + i * 256] = tf32_rna(vals[i] * inv);
}

// ---------------- launcher --------------------------------------------------
extern "C" void kernel_launch(void* const* d_in, const int* in_sizes, int n_in,
                              void* d_out, int out_size)
{
    (void)in_sizes; (void)n_in; (void)out_size;
    const float* query     = (const float*)d_in[0];
    const float* key_value = (const float*)d_in[1];
    const float* Wq = (const float*)d_in[2];
    const float* bq = (const float*)d_in[3];
    const float* Wk = (const float*)d_in[4];
    const float* bk = (const float*)d_in[5];
    const float* Wv = (const float*)d_in[6];
    const float* bv = (const float*)d_in[7];
    const float* Wo = (const float*)d_in[8];
    const float* bo = (const float*)d_in[9];
    float* out = (float*)d_out;

    float *qry_hi, *qry_lo, *kv_hi, *kv_lo, *q_hi, *q_lo, *k_hi, *k_lo;
    float *vt, *s, *o;
    float *wqt_hi, *wqt_lo, *wkt_hi, *wkt_lo, *wvt, *wot;
    cudaGetSymbolAddress((void**)&qry_hi, g_query_hi);
    cudaGetSymbolAddress((void**)&qry_lo, g_query_lo);
    cudaGetSymbolAddress((void**)&kv_hi,  g_kv_hi);
    cudaGetSymbolAddress((void**)&kv_lo,  g_kv_lo);
    cudaGetSymbolAddress((void**)&q_hi,   g_q_hi);
    cudaGetSymbolAddress((void**)&q_lo,   g_q_lo);
    cudaGetSymbolAddress((void**)&k_hi,   g_k_hi);
    cudaGetSymbolAddress((void**)&k_lo,   g_k_lo);
    cudaGetSymbolAddress((void**)&vt,     g_vt);
    cudaGetSymbolAddress((void**)&s,      g_s);
    cudaGetSymbolAddress((void**)&o,      g_o);
    cudaGetSymbolAddress((void**)&wqt_hi, g_wqt_hi);
    cudaGetSymbolAddress((void**)&wqt_lo, g_wqt_lo);
    cudaGetSymbolAddress((void**)&wkt_hi, g_wkt_hi);
    cudaGetSymbolAddress((void**)&wkt_lo, g_wkt_lo);
    cudaGetSymbolAddress((void**)&wvt,    g_wvt);
    cudaGetSymbolAddress((void**)&wot,    g_wot);

    constexpr int SM3 = 2 * 4 * TILE_B;   // 81920 B
    constexpr int SM1 = 2 * 2 * TILE_B;   // 40960 B
    cudaFuncSetAttribute(gemm_mma<3,0>, cudaFuncAttributeMaxDynamicSharedMemorySize, SM3);
    cudaFuncSetAttribute(gemm_mma<3,2>, cudaFuncAttributeMaxDynamicSharedMemorySize, SM3);
    cudaFuncSetAttribute(gemm_mma<1,1>, cudaFuncAttributeMaxDynamicSharedMemorySize, SM1);
    cudaFuncSetAttribute(gemm_mma<1,3>, cudaFuncAttributeMaxDynamicSharedMemorySize, SM1);
    cudaFuncSetAttribute(gemm_mma<1,4>, cudaFuncAttributeMaxDynamicSharedMemorySize, SM1);

    const size_t sQKV = (size_t)SEQ * DIM;
    const size_t sS   = (size_t)SEQ * SEQ;
    const size_t sVT  = (size_t)DIM * SEQ;
    const int n4 = BB * SEQ * DIM / 4;

    // prep: splits + weight transposes
    split_arr<<<(n4 + 255) / 256, 256>>>((const float4*)query,     (float4*)qry_hi, (float4*)qry_lo, n4);
    split_arr<<<(n4 + 255) / 256, 256>>>((const float4*)key_value, (float4*)kv_hi,  (float4*)kv_lo,  n4);
    wprep<true ><<<1024, 256>>>(Wq, wqt_hi, wqt_lo);
    wprep<true ><<<1024, 256>>>(Wk, wkt_hi, wkt_lo);
    wprep<false><<<1024, 256>>>(Wv, wvt, nullptr);
    wprep<false><<<1024, 256>>>(Wo, wot, nullptr);

    // G1/G2: q,k projections (3xTF32, split epilogue)
    {
        dim3 grid(DIM / 128, (BB * SEQ) / 128, 1);
        gemm_mma<3,0><<<grid, 256, SM3>>>(qry_hi, qry_lo, wqt_hi, wqt_lo,
            q_hi, q_lo, bq, nullptr, DIM, DIM, DIM, DIM, 0, 0, 0, 1.0f);
        gemm_mma<3,0><<<grid, 256, SM3>>>(kv_hi, kv_lo, wkt_hi, wkt_lo,
            k_hi, k_lo, bk, nullptr, DIM, DIM, DIM, DIM, 0, 0, 0, 1.0f);
        // G3: v projection -> transposed VT (1x)
        gemm_mma<1,1><<<grid, 256, SM1>>>(kv_hi, nullptr, wvt, nullptr,
            vt, nullptr, bv, nullptr, DIM, DIM, DIM, 0, 0, 0, 0, 1.0f);
    }

    // G4: S = sqrt(512) * q @ k^T (3xTF32, batched)
    {
        dim3 grid(SEQ / 128, SEQ / 128, BB);
        gemm_mma<3,2><<<grid, 256, SM3>>>(q_hi, q_lo, k_hi, k_lo,
            s, nullptr, nullptr, nullptr, DIM, DIM, DIM, SEQ,
            sQKV, sQKV, sS, SCALE_F);
    }

    softmax_rows<<<BB * SEQ, 256>>>(s);

    // G5: O = P @ V (1x, batched), B = VT
    {
        dim3 grid(DIM / 128, SEQ / 128, BB);
        gemm_mma<1,3><<<grid, 256, SM1>>>(s, nullptr, vt, nullptr,
            o, nullptr, nullptr, nullptr, SEQ, SEQ, SEQ, DIM,
            sS, sVT, sQKV, 1.0f);
    }

    // G6: out = query + O @ Wo + bo (1x)
    {
        dim3 grid(DIM / 128, (BB * SEQ) / 128, 1);
        gemm_mma<1,4><<<grid, 256, SM1>>>(o, nullptr, wot, nullptr,
            out, nullptr, bo, query, DIM, DIM, DIM, DIM, 0, 0, 0, 1.0f);
    }
}

// round 4
// speedup vs baseline: 1.8148x; 1.0412x over previous
#include <cuda_runtime.h>
#include <cstdint>

// ===========================================================================
// AxisAttention via mma.sync tf32, k-permuted float2-fragment layout.
// 3xTF32 split precision for q/k projections and QK^T; single-pass tf32 for
// v-proj, PV, out-proj. B=4, N=2048, D=DA=512.
// ===========================================================================

constexpr int BB  = 4;
constexpr int SEQ = 2048;
constexpr int DIM = 512;
constexpr float SCALE_F = 22.62741699796952f;  // sqrt(512), multiplied

// ---------------- device global scratch (no runtime allocation) -----------
__device__ float g_query_hi[(size_t)BB * SEQ * DIM];
__device__ float g_query_lo[(size_t)BB * SEQ * DIM];
__device__ float g_kv_hi[(size_t)BB * SEQ * DIM];
__device__ float g_kv_lo[(size_t)BB * SEQ * DIM];
__device__ float g_q_hi[(size_t)BB * SEQ * DIM];
__device__ float g_q_lo[(size_t)BB * SEQ * DIM];
__device__ float g_k_hi[(size_t)BB * SEQ * DIM];
__device__ float g_k_lo[(size_t)BB * SEQ * DIM];
__device__ float g_vt[(size_t)BB * DIM * SEQ];        // V^T per batch [DIM, SEQ]
__device__ float g_s[(size_t)BB * SEQ * SEQ];         // scores / probs
__device__ float g_o[(size_t)BB * SEQ * DIM];
__device__ float g_wqt_hi[DIM * DIM];
__device__ float g_wqt_lo[DIM * DIM];
__device__ float g_wkt_hi[DIM * DIM];
__device__ float g_wkt_lo[DIM * DIM];
__device__ float g_wvt[DIM * DIM];
__device__ float g_wot[DIM * DIM];

// ---------------- helpers ---------------------------------------------------
__device__ __forceinline__ uint32_t smem_u32(const void* p) {
    uint32_t a;
    asm("{ .reg .u64 t; cvta.to.shared.u64 t, %1; cvt.u32.u64 %0, t; }"
        : "=r"(a) : "l"(p));
    return a;
}
__device__ __forceinline__ float tf32_rna(float x) {
    uint32_t u;
    asm("cvt.rna.tf32.f32 %0, %1;" : "=r"(u) : "f"(x));
    return __uint_as_float(u);
}
__device__ __forceinline__ void cp16(uint32_t saddr, const void* g) {
    asm volatile("cp.async.cg.shared.global [%0], [%1], 16;"
                 :: "r"(saddr), "l"(g) : "memory");
}
__device__ __forceinline__ void cp_commit() {
    asm volatile("cp.async.commit_group;" ::: "memory");
}
template <int N>
__device__ __forceinline__ void cp_wait() {
    asm volatile("cp.async.wait_group %0;" :: "n"(N) : "memory");
}

// k-permutation within each 16-block: (t, t+4) -> (2t, 2t+1) in each half.
__device__ __forceinline__ int perm16(int t) {
    const int lo = t & 7;
    return (t & 8) + 2 * (lo & 3) + (lo >> 2);
}
__device__ __forceinline__ int permk(int k) {
    return (k & ~15) | perm16(k & 15);
}

// mma.sync m16n8k8 tf32
__device__ __forceinline__ void mma8(float* c, float a0, float a1, float a2,
                                     float a3, float b0, float b1) {
    asm volatile(
        "mma.sync.aligned.m16n8k8.row.col.f32.tf32.tf32.f32 "
        "{%0,%1,%2,%3}, {%4,%5,%6,%7}, {%8,%9}, {%0,%1,%2,%3};"
        : "+f"(c[0]), "+f"(c[1]), "+f"(c[2]), "+f"(c[3])
        : "r"(__float_as_uint(a0)), "r"(__float_as_uint(a1)),
          "r"(__float_as_uint(a2)), "r"(__float_as_uint(a3)),
          "r"(__float_as_uint(b0)), "r"(__float_as_uint(b1)));
}

// ---------------- tiles: 128 rows x 32 k-floats, row stride 40 floats ------
constexpr int LDW    = 40;
constexpr int TILE_F = 128 * LDW;     // 5120 floats
constexpr int TILE_B = TILE_F * 4;    // 20480 bytes

__device__ __forceinline__ void load_tile32(
    uint32_t sbase, const float* __restrict__ g, int ld, int tid)
{
#pragma unroll
    for (int i = 0; i < 4; i++) {
        const int f  = tid + i * 256;     // 0..1023 float4s
        const int r  = f >> 3;
        const int c4 = (f & 7) << 2;
        cp16(sbase + (uint32_t)(r * LDW + c4) * 4, g + (size_t)r * ld + c4);
    }
}

// ---------------- main GEMM -------------------------------------------------
// D[m,n] = alpha * sum_k A[m,k]*B[n,k] (+bias[n]) (+resid), 128x128 CTA tile,
// K-chunk 32, 8 warps, warp tile 64x32. Operand k-dims are perm-layout.
// EPI: 0=split hi/lo+bias (perm cols), 1=transposed VT+bias (perm seq),
// 2=alpha scale (perm cols), 3=plain tf32 (perm cols), 4=bias+residual.
template <int PASSES, int EPI>
__global__ void __launch_bounds__(256, (PASSES == 3) ? 1 : 2) gemm_mma(
    const float* __restrict__ Ahi, const float* __restrict__ Alo,
    const float* __restrict__ Bhi, const float* __restrict__ Blo,
    float* __restrict__ C, float* __restrict__ C2,
    const float* __restrict__ bias, const float* __restrict__ resid,
    int K, int lda, int ldb, int ldc,
    size_t sA, size_t sB, size_t sC, float alpha)
{
    constexpr int NT = (PASSES == 3) ? 4 : 2;   // tiles per stage
    extern __shared__ float smf[];
    const uint32_t sb = smem_u32(smf);

    const int tid    = threadIdx.x;
    const int lane   = tid & 31;
    const int wid    = tid >> 5;
    const int warp_m = wid >> 2;      // 0..1
    const int warp_n = wid & 3;       // 0..3
    const int n0 = blockIdx.x * 128;
    const int m0 = blockIdx.y * 128;
    const int z  = blockIdx.z;

    const float* A0 = Ahi + (size_t)z * sA + (size_t)m0 * lda;
    const float* B0 = Bhi + (size_t)z * sB + (size_t)n0 * ldb;
    const float* A1 = (PASSES == 3) ? Alo + (size_t)z * sA + (size_t)m0 * lda : nullptr;
    const float* B1 = (PASSES == 3) ? Blo + (size_t)z * sB + (size_t)n0 * ldb : nullptr;

    float acc[4][4][4];
#pragma unroll
    for (int i = 0; i < 4; i++)
#pragma unroll
        for (int j = 0; j < 4; j++)
#pragma unroll
            for (int l = 0; l < 4; l++) acc[i][j][l] = 0.0f;

    const int nch = K / 32;

    auto load_stage = [&](int buf, int c) {
        const uint32_t st = sb + (uint32_t)buf * NT * TILE_B;
        load_tile32(st,              A0 + c * 32, lda, tid);
        load_tile32(st + TILE_B,     B0 + c * 32, ldb, tid);
        if (PASSES == 3) {
            load_tile32(st + 2 * TILE_B, A1 + c * 32, lda, tid);
            load_tile32(st + 3 * TILE_B, B1 + c * 32, ldb, tid);
        }
    };

    load_stage(0, 0);
    cp_commit();

    const int arow0 = warp_m * 64 + (lane >> 2);
    const int bcol0 = warp_n * 32 + (lane >> 2);
    const int kq2   = 2 * (lane & 3);

    for (int c = 0; c < nch; c++) {
        if (c + 1 < nch) {
            load_stage((c + 1) & 1, c + 1);
            cp_commit();
            cp_wait<1>();
        } else {
            cp_wait<0>();
        }
        __syncthreads();

        const float* st  = smf + (size_t)(c & 1) * NT * TILE_F;
        const float* Ath = st;
        const float* Bth = st + TILE_F;
        const float* Atl = st + 2 * TILE_F;
        const float* Btl = st + 3 * TILE_F;

#pragma unroll
        for (int s = 0; s < 4; s++) {
            const int ko = s * 8 + kq2;
            float2 a0[4], a1[4], b0[4];
#pragma unroll
            for (int i = 0; i < 4; i++) {
                a0[i] = *reinterpret_cast<const float2*>(
                    Ath + (size_t)(arow0 + i * 16) * LDW + ko);
                a1[i] = *reinterpret_cast<const float2*>(
                    Ath + (size_t)(arow0 + i * 16 + 8) * LDW + ko);
            }
#pragma unroll
            for (int j = 0; j < 4; j++)
                b0[j] = *reinterpret_cast<const float2*>(
                    Bth + (size_t)(bcol0 + j * 8) * LDW + ko);
#pragma unroll
            for (int i = 0; i < 4; i++)
#pragma unroll
                for (int j = 0; j < 4; j++)
                    mma8(acc[i][j], a0[i].x, a1[i].x, a0[i].y, a1[i].y,
                         b0[j].x, b0[j].y);

            if (PASSES == 3) {
                float2 bl[4];
#pragma unroll
                for (int j = 0; j < 4; j++)
                    bl[j] = *reinterpret_cast<const float2*>(
                        Btl + (size_t)(bcol0 + j * 8) * LDW + ko);
#pragma unroll
                for (int i = 0; i < 4; i++)
#pragma unroll
                    for (int j = 0; j < 4; j++)
                        mma8(acc[i][j], a0[i].x, a1[i].x, a0[i].y, a1[i].y,
                             bl[j].x, bl[j].y);
                float2 al0[4], al1[4];
#pragma unroll
                for (int i = 0; i < 4; i++) {
                    al0[i] = *reinterpret_cast<const float2*>(
                        Atl + (size_t)(arow0 + i * 16) * LDW + ko);
                    al1[i] = *reinterpret_cast<const float2*>(
                        Atl + (size_t)(arow0 + i * 16 + 8) * LDW + ko);
                }
#pragma unroll
                for (int i = 0; i < 4; i++)
#pragma unroll
                    for (int j = 0; j < 4; j++)
                        mma8(acc[i][j], al0[i].x, al1[i].x, al0[i].y, al1[i].y,
                             b0[j].x, b0[j].y);
            }
        }
        __syncthreads();
    }

    // ---------------- epilogue ----------------
    float* Cz = C + (size_t)z * sC;
#pragma unroll
    for (int i = 0; i < 4; i++) {
#pragma unroll
        for (int j = 0; j < 4; j++) {
            const float* a4 = acc[i][j];
            const int r0 = m0 + warp_m * 64 + i * 16 + (lane >> 2);
            const int c0 = n0 + warp_n * 32 + j * 8 + 2 * (lane & 3);
            if (EPI == 0) {            // split hi/lo + bias, perm cols
                float* C2z = C2 + (size_t)z * sC;
                const float bx = bias[c0], by = bias[c0 + 1];
                const int p0 = permk(c0), p1 = permk(c0 + 1);
                const float v0 = a4[0] + bx, v1 = a4[1] + by;
                const float v2 = a4[2] + bx, v3 = a4[3] + by;
                float h;
                h = tf32_rna(v0); Cz[(size_t)r0 * ldc + p0] = h;
                C2z[(size_t)r0 * ldc + p0] = tf32_rna(v0 - h);
                h = tf32_rna(v1); Cz[(size_t)r0 * ldc + p1] = h;
                C2z[(size_t)r0 * ldc + p1] = tf32_rna(v1 - h);
                h = tf32_rna(v2); Cz[(size_t)(r0 + 8) * ldc + p0] = h;
                C2z[(size_t)(r0 + 8) * ldc + p0] = tf32_rna(v2 - h);
                h = tf32_rna(v3); Cz[(size_t)(r0 + 8) * ldc + p1] = h;
                C2z[(size_t)(r0 + 8) * ldc + p1] = tf32_rna(v3 - h);
            } else if (EPI == 1) {     // transposed VT[b][dim][seq], perm seq
                const float bx = bias[c0], by = bias[c0 + 1];
                const int b0i = r0 >> 11,        sx0 = permk(r0 & (SEQ - 1));
                const int b1i = (r0 + 8) >> 11,  sx1 = permk((r0 + 8) & (SEQ - 1));
                float* p0 = C + (size_t)b0i * DIM * SEQ;
                float* p1 = C + (size_t)b1i * DIM * SEQ;
                p0[(size_t)c0 * SEQ + sx0]       = tf32_rna(a4[0] + bx);
                p0[(size_t)(c0 + 1) * SEQ + sx0] = tf32_rna(a4[1] + by);
                p1[(size_t)c0 * SEQ + sx1]       = tf32_rna(a4[2] + bx);
                p1[(size_t)(c0 + 1) * SEQ + sx1] = tf32_rna(a4[3] + by);
            } else if (EPI == 2) {     // alpha scale (scores), perm cols
                const int p0 = permk(c0), p1 = permk(c0 + 1);
                Cz[(size_t)r0 * ldc + p0]       = alpha * a4[0];
                Cz[(size_t)r0 * ldc + p1]       = alpha * a4[1];
                Cz[(size_t)(r0 + 8) * ldc + p0] = alpha * a4[2];
                Cz[(size_t)(r0 + 8) * ldc + p1] = alpha * a4[3];
            } else if (EPI == 3) {     // plain tf32-rounded (O), perm cols
                const int p0 = permk(c0), p1 = permk(c0 + 1);
                Cz[(size_t)r0 * ldc + p0]       = tf32_rna(a4[0]);
                Cz[(size_t)r0 * ldc + p1]       = tf32_rna(a4[1]);
                Cz[(size_t)(r0 + 8) * ldc + p0] = tf32_rna(a4[2]);
                Cz[(size_t)(r0 + 8) * ldc + p1] = tf32_rna(a4[3]);
            } else {                   // bias + residual (final out), no perm
                const float bx = bias[c0], by = bias[c0 + 1];
                const float2 rs0 = *reinterpret_cast<const float2*>(
                    &resid[(size_t)r0 * ldc + c0]);
                const float2 rs1 = *reinterpret_cast<const float2*>(
                    &resid[(size_t)(r0 + 8) * ldc + c0]);
                float2 v0, v1;
                v0.x = a4[0] + bx + rs0.x; v0.y = a4[1] + by + rs0.y;
                v1.x = a4[2] + bx + rs1.x; v1.y = a4[3] + by + rs1.y;
                *reinterpret_cast<float2*>(&Cz[(size_t)r0 * ldc + c0]) = v0;
                *reinterpret_cast<float2*>(&Cz[(size_t)(r0 + 8) * ldc + c0]) = v1;
            }
        }
    }
}

// ---------------- prep: fused splits (query + key_value), perm k -----------
__global__ void split_two(const float4* __restrict__ q, const float4* __restrict__ kv,
                          float* __restrict__ qh, float* __restrict__ ql,
                          float* __restrict__ kh, float* __restrict__ kl, int n4)
{
    int id = blockIdx.x * 256 + threadIdx.x;
    const float4* src; float *dh, *dl;
    if (id < n4) { src = q; dh = qh; dl = ql; }
    else         { src = kv; dh = kh; dl = kl; id -= n4; if (id >= n4) return; }
    const float4 v = src[id];
    const int e0 = id * 4;
    const int base = e0 & ~511;        // row start (DIM=512 divides rows)
    float vv[4] = {v.x, v.y, v.z, v.w};
#pragma unroll
    for (int u = 0; u < 4; u++) {
        const int k = (e0 + u) & 511;
        const int pk = permk(k);
        const float h = tf32_rna(vv[u]);
        dh[base + pk] = h;
        dl[base + pk] = tf32_rna(vv[u] - h);
    }
}

// ---------------- prep: fused weight transposes, perm k --------------------
__global__ void wprep_all(const float* __restrict__ Wq, const float* __restrict__ Wk,
                          const float* __restrict__ Wv, const float* __restrict__ Wo,
                          float* __restrict__ qh, float* __restrict__ ql,
                          float* __restrict__ kh, float* __restrict__ kl,
                          float* __restrict__ vh, float* __restrict__ oh)
{
    const int idx = blockIdx.x * 256 + threadIdx.x;  // 0 .. 512*512-1
    const int wsel = blockIdx.y;                     // 0..3
    const int n = idx & 511;        // coalesced read over n
    const int k = idx >> 9;
    const float* W; float *Th, *Tl;
    if      (wsel == 0) { W = Wq; Th = qh; Tl = ql; }
    else if (wsel == 1) { W = Wk; Th = kh; Tl = kl; }
    else if (wsel == 2) { W = Wv; Th = vh; Tl = nullptr; }
    else                { W = Wo; Th = oh; Tl = nullptr; }
    const float w = W[(size_t)k * DIM + n];
    const float h = tf32_rna(w);
    const size_t dst = (size_t)n * DIM + permk(k);
    Th[dst] = h;
    if (Tl) Tl[dst] = tf32_rna(w - h);
}

// ---------------- softmax (rows of 2048), output tf32-rounded --------------
__global__ void __launch_bounds__(256) softmax_rows(float* __restrict__ S)
{
    const size_t row = blockIdx.x;
    float* p = S + row * (size_t)SEQ;
    const int t = threadIdx.x;
    float vals[8];
    float m = -3.402823466e38f;
#pragma unroll
    for (int i = 0; i < 8; i++) { vals[i] = p[t + i * 256]; m = fmaxf(m, vals[i]); }
    __shared__ float red[256];
    red[t] = m; __syncthreads();
#pragma unroll
    for (int s = 128; s > 0; s >>= 1) { if (t < s) red[t] = fmaxf(red[t], red[t+s]); __syncthreads(); }
    m = red[0]; __syncthreads();
    float sum = 0.0f;
#pragma unroll
    for (int i = 0; i < 8; i++) { vals[i] = __expf(vals[i] - m); sum += vals[i]; }
    red[t] = sum; __syncthreads();
#pragma unroll
    for (int s = 128; s > 0; s >>= 1) { if (t < s) red[t] += red[t+s]; __syncthreads(); }
    const float inv = 1.0f / red[0];
#pragma unroll
    for (int i = 0; i < 8; i++) p[t + i * 256] = tf32_rna(vals[i] * inv);
}

// ---------------- launcher --------------------------------------------------
extern "C" void kernel_launch(void* const* d_in, const int* in_sizes, int n_in,
                              void* d_out, int out_size)
{
    (void)in_sizes; (void)n_in; (void)out_size;
    const float* query     = (const float*)d_in[0];
    const float* key_value = (const float*)d_in[1];
    const float* Wq = (const float*)d_in[2];
    const float* bq = (const float*)d_in[3];
    const float* Wk = (const float*)d_in[4];
    const float* bk = (const float*)d_in[5];
    const float* Wv = (const float*)d_in[6];
    const float* bv = (const float*)d_in[7];
    const float* Wo = (const float*)d_in[8];
    const float* bo = (const float*)d_in[9];
    float* out = (float*)d_out;

    float *qry_hi, *qry_lo, *kv_hi, *kv_lo, *q_hi, *q_lo, *k_hi, *k_lo;
    float *vt, *s, *o;
    float *wqt_hi, *wqt_lo, *wkt_hi, *wkt_lo, *wvt, *wot;
    cudaGetSymbolAddress((void**)&qry_hi, g_query_hi);
    cudaGetSymbolAddress((void**)&qry_lo, g_query_lo);
    cudaGetSymbolAddress((void**)&kv_hi,  g_kv_hi);
    cudaGetSymbolAddress((void**)&kv_lo,  g_kv_lo);
    cudaGetSymbolAddress((void**)&q_hi,   g_q_hi);
    cudaGetSymbolAddress((void**)&q_lo,   g_q_lo);
    cudaGetSymbolAddress((void**)&k_hi,   g_k_hi);
    cudaGetSymbolAddress((void**)&k_lo,   g_k_lo);
    cudaGetSymbolAddress((void**)&vt,     g_vt);
    cudaGetSymbolAddress((void**)&s,      g_s);
    cudaGetSymbolAddress((void**)&o,      g_o);
    cudaGetSymbolAddress((void**)&wqt_hi, g_wqt_hi);
    cudaGetSymbolAddress((void**)&wqt_lo, g_wqt_lo);
    cudaGetSymbolAddress((void**)&wkt_hi, g_wkt_hi);
    cudaGetSymbolAddress((void**)&wkt_lo, g_wkt_lo);
    cudaGetSymbolAddress((void**)&wvt,    g_wvt);
    cudaGetSymbolAddress((void**)&wot,    g_wot);

    constexpr int SM3 = 2 * 4 * TILE_B;   // 163840 B
    constexpr int SM1 = 2 * 2 * TILE_B;   // 81920 B
    cudaFuncSetAttribute(gemm_mma<3,0>, cudaFuncAttributeMaxDynamicSharedMemorySize, SM3);
    cudaFuncSetAttribute(gemm_mma<3,2>, cudaFuncAttributeMaxDynamicSharedMemorySize, SM3);
    cudaFuncSetAttribute(gemm_mma<1,1>, cudaFuncAttributeMaxDynamicSharedMemorySize, SM1);
    cudaFuncSetAttribute(gemm_mma<1,3>, cudaFuncAttributeMaxDynamicSharedMemorySize, SM1);
    cudaFuncSetAttribute(gemm_mma<1,4>, cudaFuncAttributeMaxDynamicSharedMemorySize, SM1);

    const size_t sQKV = (size_t)SEQ * DIM;
    const size_t sS   = (size_t)SEQ * SEQ;
    const size_t sVT  = (size_t)DIM * SEQ;
    const int n4 = BB * SEQ * DIM / 4;

    // prep (2 launches so that launch #5 = G4 for ncu -s 5 -c 1)
    split_two<<<(2 * n4 + 255) / 256, 256>>>((const float4*)query,
        (const float4*)key_value, qry_hi, qry_lo, kv_hi, kv_lo, n4);
    {
        dim3 g((DIM * DIM) / 256, 4);
        wprep_all<<<g, 256>>>(Wq, Wk, Wv, Wo,
                              wqt_hi, wqt_lo, wkt_hi, wkt_lo, wvt, wot);
    }

    // G1/G2: q,k projections (3xTF32, split epilogue)
    {
        dim3 grid(DIM / 128, (BB * SEQ) / 128, 1);
        gemm_mma<3,0><<<grid, 256, SM3>>>(qry_hi, qry_lo, wqt_hi, wqt_lo,
            q_hi, q_lo, bq, nullptr, DIM, DIM, DIM, DIM, 0, 0, 0, 1.0f);
        gemm_mma<3,0><<<grid, 256, SM3>>>(kv_hi, kv_lo, wkt_hi, wkt_lo,
            k_hi, k_lo, bk, nullptr, DIM, DIM, DIM, DIM, 0, 0, 0, 1.0f);
        // G3: v projection -> transposed VT (1x)
        gemm_mma<1,1><<<grid, 256, SM1>>>(kv_hi, nullptr, wvt, nullptr,
            vt, nullptr, bv, nullptr, DIM, DIM, DIM, 0, 0, 0, 0, 1.0f);
    }

    // G4: S = sqrt(512) * q @ k^T (3xTF32, batched)  [launch index 5]
    {
        dim3 grid(SEQ / 128, SEQ / 128, BB);
        gemm_mma<3,2><<<grid, 256, SM3>>>(q_hi, q_lo, k_hi, k_lo,
            s, nullptr, nullptr, nullptr, DIM, DIM, DIM, SEQ,
            sQKV, sQKV, sS, SCALE_F);
    }

    softmax_rows<<<BB * SEQ, 256>>>(s);

    // G5: O = P @ V (1x, batched), B = VT
    {
        dim3 grid(DIM / 128, SEQ / 128, BB);
        gemm_mma<1,3><<<grid, 256, SM1>>>(s, nullptr, vt, nullptr,
            o, nullptr, nullptr, nullptr, SEQ, SEQ, SEQ, DIM,
            sS, sVT, sQKV, 1.0f);
    }

    // G6: out = query + O @ Wo + bo (1x)
    {
        dim3 grid(DIM / 128, (BB * SEQ) / 128, 1);
        gemm_mma<1,4><<<grid, 256, SM1>>>(o, nullptr, wot, nullptr,
            out, nullptr, bo, query, DIM, DIM, DIM, DIM, 0, 0, 0, 1.0f);
    }
}